// round 2
// baseline (speedup 1.0000x reference)
#include <cuda_runtime.h>
#include <math_constants.h>

#define B_  4
#define S_  4096
#define D_  256
#define H_  4
#define DH_ 64
#define MT_ (B_ * S_)   // 16384 rows

typedef unsigned long long u64;

// ---------------------------------------------------------------------------
// f32x2 packed helpers (sm_103a FFMA2 path)
// ---------------------------------------------------------------------------
__device__ __forceinline__ u64 fma2(u64 a, u64 b, u64 c) {
    u64 d; asm("fma.rn.f32x2 %0,%1,%2,%3;" : "=l"(d) : "l"(a), "l"(b), "l"(c));
    return d;
}
__device__ __forceinline__ u64 mul2(u64 a, u64 b) {
    u64 d; asm("mul.rn.f32x2 %0,%1,%2;" : "=l"(d) : "l"(a), "l"(b));
    return d;
}
__device__ __forceinline__ u64 dup2(float x) {
    u64 d; asm("mov.b64 %0,{%1,%1};" : "=l"(d) : "f"(x));
    return d;
}
__device__ __forceinline__ float2 unpk(u64 v) {
    float2 r; asm("mov.b64 {%0,%1},%2;" : "=f"(r.x), "=f"(r.y) : "l"(v));
    return r;
}

// ---------------------------------------------------------------------------
// Scratch (static device globals; no runtime allocation allowed)
// ---------------------------------------------------------------------------
__device__ float g_Q[(size_t)B_ * H_ * S_ * DH_];   // [b][h][s][dh], pre-scaled 1/8
__device__ float g_K[(size_t)B_ * H_ * S_ * DH_];
__device__ float g_V[(size_t)B_ * H_ * S_ * DH_];
__device__ float g_attn[(size_t)B_ * S_ * D_];

// ---------------------------------------------------------------------------
// Kernel 1: fused QKV projection. Tile 128(m) x 64(n==head), k-block 32.
// block 256 = 32 row-groups(x4) x 8 col-groups(x8). f32x2 accumulators.
// grid (MT/128, H, 3)
// ---------------------------------------------------------------------------
__global__ void __launch_bounds__(256) qkv_gemm(
    const float* __restrict__ X,
    const float* __restrict__ Wq, const float* __restrict__ bq,
    const float* __restrict__ Wk, const float* __restrict__ bk,
    const float* __restrict__ Wv, const float* __restrict__ bv)
{
    __shared__ float Xt[32][132];   // k-major: Xt[k][m]
    __shared__ float Ws[32][68];    // natural: Ws[k][n]

    const float* W; const float* bias; float* out; float qscale;
    if (blockIdx.z == 0)      { W = Wq; bias = bq; out = g_Q; qscale = 0.125f; }
    else if (blockIdx.z == 1) { W = Wk; bias = bk; out = g_K; qscale = 1.0f;   }
    else                      { W = Wv; bias = bv; out = g_V; qscale = 1.0f;   }

    const int m0  = blockIdx.x * 128;
    const int h   = blockIdx.y;
    const int n0  = h * 64;
    const int tid = threadIdx.x;
    const int tx  = tid & 7;    // col group: 8 cols
    const int ty  = tid >> 3;   // row group: 4 rows

    u64 acc[4][4];
    #pragma unroll
    for (int i = 0; i < 4; i++)
        #pragma unroll
        for (int j = 0; j < 4; j++) acc[i][j] = 0ull;

    for (int kk = 0; kk < D_; kk += 32) {
        // X tile: 128 x 32, load float4 along k, store transposed
        #pragma unroll
        for (int it = 0; it < 4; it++) {
            int idx = tid + it * 256;          // < 1024
            int r = idx >> 3, k4 = idx & 7;
            float4 v = *(const float4*)&X[(size_t)(m0 + r) * D_ + kk + k4 * 4];
            Xt[k4 * 4 + 0][r] = v.x;
            Xt[k4 * 4 + 1][r] = v.y;
            Xt[k4 * 4 + 2][r] = v.z;
            Xt[k4 * 4 + 3][r] = v.w;
        }
        // W tile: 32 x 64
        #pragma unroll
        for (int it = 0; it < 2; it++) {
            int idx = tid + it * 256;          // < 512
            int kr = idx >> 4, n4 = idx & 15;
            *(float4*)&Ws[kr][n4 * 4] =
                *(const float4*)&W[(size_t)(kk + kr) * D_ + n0 + n4 * 4];
        }
        __syncthreads();
        #pragma unroll
        for (int k = 0; k < 32; k++) {
            float4 a4 = *(const float4*)&Xt[k][ty * 4];
            ulonglong2 bA = *(const ulonglong2*)&Ws[k][tx * 8];
            ulonglong2 bB = *(const ulonglong2*)&Ws[k][tx * 8 + 4];
            u64 bw[4] = {bA.x, bA.y, bB.x, bB.y};
            u64 av[4] = {dup2(a4.x), dup2(a4.y), dup2(a4.z), dup2(a4.w)};
            #pragma unroll
            for (int i = 0; i < 4; i++)
                #pragma unroll
                for (int j = 0; j < 4; j++)
                    acc[i][j] = fma2(av[i], bw[j], acc[i][j]);
        }
        __syncthreads();
    }

    // epilogue: head-split layout [b][h][s][dh], Q pre-scaled
    const int bb    = m0 >> 12;
    const int sbase = m0 & (S_ - 1);
    #pragma unroll
    for (int i = 0; i < 4; i++) {
        const int s = sbase + ty * 4 + i;
        float* op = out + ((size_t)(bb * H_ + h) * S_ + s) * DH_ + tx * 8;
        #pragma unroll
        for (int j = 0; j < 4; j++) {
            float2 p = unpk(acc[i][j]);
            int dh = tx * 8 + j * 2;
            float2 r;
            r.x = (p.x + bias[n0 + dh + 0]) * qscale;
            r.y = (p.y + bias[n0 + dh + 1]) * qscale;
            *(float2*)&op[j * 2] = r;
        }
    }
}

// ---------------------------------------------------------------------------
// Kernel 2: flash attention, fp32 f32x2, online softmax.
// Tile: BQ=128 q rows, BK=64 k cols, Dh=64. block 256, grid (S/128, B*H).
// ---------------------------------------------------------------------------
#define ATTN_SMEM_FLOATS (64*132 + 64*68 + 64*68 + 128*68 + 3*128 + 256)
#define ATTN_SMEM_BYTES  (ATTN_SMEM_FLOATS * 4)

__global__ void __launch_bounds__(256, 2) attn_kernel()
{
    extern __shared__ float sm[];
    float (*Qt)[132] = (float(*)[132])(sm);                       // Qt[d][r] r<128
    float (*Kt)[68]  = (float(*)[68]) (sm + 64 * 132);            // Kt[d][c] c<64
    float (*Vs)[68]  = (float(*)[68]) (sm + 64 * 132 + 64 * 68);  // Vs[k][c]
    float (*Ps)[68]  = (float(*)[68]) (sm + 64 * 132 + 2 * 64 * 68); // Ps[r][k]
    float* m_s  = sm + 64 * 132 + 2 * 64 * 68 + 128 * 68;
    float* l_s  = m_s + 128;
    float* c_s  = l_s + 128;
    float* red  = c_s + 128;   // 256

    const int tid = threadIdx.x;
    const int tx  = tid & 7;    // 8 col-groups x 8
    const int ty  = tid >> 3;   // 32 row-groups x 4
    const int rr  = tid >> 1;   // softmax: 2 threads / row, 128 rows
    const int qq  = tid & 1;    // each handles 32 cols
    const int bh  = blockIdx.y;
    const int q0  = blockIdx.x * 128;

    const float* Qg = g_Q + (size_t)bh * S_ * DH_;
    const float* Kg = g_K + (size_t)bh * S_ * DH_;
    const float* Vg = g_V + (size_t)bh * S_ * DH_;

    // load Q tile (128 x 64) transposed; pre-scaled by 1/8 already
    #pragma unroll
    for (int it = 0; it < 8; it++) {
        int idx = tid + it * 256;          // < 2048
        int r = idx >> 4, d4 = idx & 15;
        float4 v = *(const float4*)&Qg[(size_t)(q0 + r) * DH_ + d4 * 4];
        Qt[d4 * 4 + 0][r] = v.x;
        Qt[d4 * 4 + 1][r] = v.y;
        Qt[d4 * 4 + 2][r] = v.z;
        Qt[d4 * 4 + 3][r] = v.w;
    }
    if (tid < 128) { m_s[tid] = -CUDART_INF_F; l_s[tid] = 0.0f; }

    u64 acc[4][4];
    #pragma unroll
    for (int i = 0; i < 4; i++)
        #pragma unroll
        for (int j = 0; j < 4; j++) acc[i][j] = 0ull;

    for (int j0 = 0; j0 < S_; j0 += 64) {
        __syncthreads();   // prev tile fully consumed; Qt/stats ready on iter 0
        // load K (transposed) and V (natural) tiles: 64 x 64 each
        #pragma unroll
        for (int it = 0; it < 4; it++) {
            int idx = tid + it * 256;      // < 1024
            int r = idx >> 4, d4 = idx & 15;
            float4 kv = *(const float4*)&Kg[(size_t)(j0 + r) * DH_ + d4 * 4];
            Kt[d4 * 4 + 0][r] = kv.x;
            Kt[d4 * 4 + 1][r] = kv.y;
            Kt[d4 * 4 + 2][r] = kv.z;
            Kt[d4 * 4 + 3][r] = kv.w;
            *(float4*)&Vs[r][d4 * 4] =
                *(const float4*)&Vg[(size_t)(j0 + r) * DH_ + d4 * 4];
        }
        __syncthreads();

        // ---- S = Q K^T (pre-scaled) ----
        u64 s2[4][4];
        #pragma unroll
        for (int i = 0; i < 4; i++)
            #pragma unroll
            for (int j = 0; j < 4; j++) s2[i][j] = 0ull;
        #pragma unroll 4
        for (int d = 0; d < 64; d++) {
            float4 a4 = *(const float4*)&Qt[d][ty * 4];
            ulonglong2 bA = *(const ulonglong2*)&Kt[d][tx * 8];
            ulonglong2 bB = *(const ulonglong2*)&Kt[d][tx * 8 + 4];
            u64 bw[4] = {bA.x, bA.y, bB.x, bB.y};
            u64 av[4] = {dup2(a4.x), dup2(a4.y), dup2(a4.z), dup2(a4.w)};
            #pragma unroll
            for (int i = 0; i < 4; i++)
                #pragma unroll
                for (int j = 0; j < 4; j++)
                    s2[i][j] = fma2(av[i], bw[j], s2[i][j]);
        }
        #pragma unroll
        for (int i = 0; i < 4; i++)
            #pragma unroll
            for (int j = 0; j < 4; j++)
                *(u64*)&Ps[ty * 4 + i][tx * 8 + j * 2] = s2[i][j];
        __syncthreads();

        // ---- online softmax (2 threads per row) ----
        {
            float mx = -CUDART_INF_F;
            #pragma unroll
            for (int c = 0; c < 32; c++)
                mx = fmaxf(mx, Ps[rr][qq * 32 + c]);
            red[rr * 2 + qq] = mx;
        }
        __syncthreads();
        if (tid < 128) {
            float m_old = m_s[tid];
            float mnew = fmaxf(fmaxf(red[tid * 2], red[tid * 2 + 1]), m_old);
            m_s[tid] = mnew;
            c_s[tid] = __expf(m_old - mnew);
        }
        __syncthreads();
        {
            float mrow = m_s[rr];
            float sum = 0.0f;
            #pragma unroll
            for (int c = 0; c < 32; c++) {
                float p = __expf(Ps[rr][qq * 32 + c] - mrow);
                Ps[rr][qq * 32 + c] = p;
                sum += p;
            }
            red[rr * 2 + qq] = sum;
        }
        __syncthreads();
        if (tid < 128) {   // runs concurrently with PV below (only touches l_s)
            l_s[tid] = l_s[tid] * c_s[tid] + red[tid * 2] + red[tid * 2 + 1];
        }

        // ---- rescale accumulator, O += P V ----
        #pragma unroll
        for (int i = 0; i < 4; i++) {
            u64 cr = dup2(c_s[ty * 4 + i]);
            #pragma unroll
            for (int j = 0; j < 4; j++)
                acc[i][j] = mul2(acc[i][j], cr);
        }
        #pragma unroll 4
        for (int k = 0; k < 64; k++) {
            ulonglong2 bA = *(const ulonglong2*)&Vs[k][tx * 8];
            ulonglong2 bB = *(const ulonglong2*)&Vs[k][tx * 8 + 4];
            u64 bw[4] = {bA.x, bA.y, bB.x, bB.y};
            u64 av[4] = {dup2(Ps[ty * 4 + 0][k]), dup2(Ps[ty * 4 + 1][k]),
                         dup2(Ps[ty * 4 + 2][k]), dup2(Ps[ty * 4 + 3][k])};
            #pragma unroll
            for (int i = 0; i < 4; i++)
                #pragma unroll
                for (int j = 0; j < 4; j++)
                    acc[i][j] = fma2(av[i], bw[j], acc[i][j]);
        }
    }
    __syncthreads();   // l_s final

    const int bb = bh >> 2, h = bh & 3;
    float* outp = g_attn + ((size_t)bb * S_ + q0) * D_ + h * DH_;
    #pragma unroll
    for (int i = 0; i < 4; i++) {
        float invl = 1.0f / l_s[ty * 4 + i];
        #pragma unroll
        for (int j = 0; j < 4; j++) {
            float2 p = unpk(acc[i][j]);
            float2 r; r.x = p.x * invl; r.y = p.y * invl;
            *(float2*)&outp[(size_t)(ty * 4 + i) * D_ + tx * 8 + j * 2] = r;
        }
    }
}

// ---------------------------------------------------------------------------
// Kernel 3: output projection. Tile 128 x 64, grid (MT/128, D/64).
// ---------------------------------------------------------------------------
__global__ void __launch_bounds__(256) out_gemm(
    const float* __restrict__ Wo, const float* __restrict__ bo,
    float* __restrict__ out)
{
    __shared__ float Xt[32][132];
    __shared__ float Ws[32][68];

    const int m0  = blockIdx.x * 128;
    const int n0  = blockIdx.y * 64;
    const int tid = threadIdx.x;
    const int tx  = tid & 7;
    const int ty  = tid >> 3;

    u64 acc[4][4];
    #pragma unroll
    for (int i = 0; i < 4; i++)
        #pragma unroll
        for (int j = 0; j < 4; j++) acc[i][j] = 0ull;

    for (int kk = 0; kk < D_; kk += 32) {
        #pragma unroll
        for (int it = 0; it < 4; it++) {
            int idx = tid + it * 256;
            int r = idx >> 3, k4 = idx & 7;
            float4 v = *(const float4*)&g_attn[(size_t)(m0 + r) * D_ + kk + k4 * 4];
            Xt[k4 * 4 + 0][r] = v.x;
            Xt[k4 * 4 + 1][r] = v.y;
            Xt[k4 * 4 + 2][r] = v.z;
            Xt[k4 * 4 + 3][r] = v.w;
        }
        #pragma unroll
        for (int it = 0; it < 2; it++) {
            int idx = tid + it * 256;
            int kr = idx >> 4, n4 = idx & 15;
            *(float4*)&Ws[kr][n4 * 4] =
                *(const float4*)&Wo[(size_t)(kk + kr) * D_ + n0 + n4 * 4];
        }
        __syncthreads();
        #pragma unroll
        for (int k = 0; k < 32; k++) {
            float4 a4 = *(const float4*)&Xt[k][ty * 4];
            ulonglong2 bA = *(const ulonglong2*)&Ws[k][tx * 8];
            ulonglong2 bB = *(const ulonglong2*)&Ws[k][tx * 8 + 4];
            u64 bw[4] = {bA.x, bA.y, bB.x, bB.y};
            u64 av[4] = {dup2(a4.x), dup2(a4.y), dup2(a4.z), dup2(a4.w)};
            #pragma unroll
            for (int i = 0; i < 4; i++)
                #pragma unroll
                for (int j = 0; j < 4; j++)
                    acc[i][j] = fma2(av[i], bw[j], acc[i][j]);
        }
        __syncthreads();
    }

    #pragma unroll
    for (int i = 0; i < 4; i++) {
        float* op = out + (size_t)(m0 + ty * 4 + i) * D_ + n0 + tx * 8;
        #pragma unroll
        for (int j = 0; j < 4; j++) {
            float2 p = unpk(acc[i][j]);
            int n = tx * 8 + j * 2;
            float2 r;
            r.x = p.x + bo[n0 + n + 0];
            r.y = p.y + bo[n0 + n + 1];
            *(float2*)&op[j * 2] = r;
        }
    }
}

// ---------------------------------------------------------------------------
// Launch
// ---------------------------------------------------------------------------
extern "C" void kernel_launch(void* const* d_in, const int* in_sizes, int n_in,
                              void* d_out, int out_size)
{
    const float* X  = (const float*)d_in[0];
    const float* Wq = (const float*)d_in[1];
    const float* bq = (const float*)d_in[2];
    const float* Wk = (const float*)d_in[3];
    const float* bk = (const float*)d_in[4];
    const float* Wv = (const float*)d_in[5];
    const float* bv = (const float*)d_in[6];
    const float* Wo = (const float*)d_in[7];
    const float* bo = (const float*)d_in[8];
    float* out = (float*)d_out;

    cudaFuncSetAttribute(attn_kernel,
                         cudaFuncAttributeMaxDynamicSharedMemorySize,
                         ATTN_SMEM_BYTES);

    qkv_gemm<<<dim3(MT_ / 128, H_, 3), 256>>>(X, Wq, bq, Wk, bk, Wv, bv);
    attn_kernel<<<dim3(S_ / 128, B_ * H_), 256, ATTN_SMEM_BYTES>>>();
    out_gemm<<<dim3(MT_ / 128, D_ / 64), 256>>>(Wo, bo, out);
}

// round 4
// speedup vs baseline: 3.9430x; 3.9430x over previous
#include <cuda_runtime.h>
#include <cuda_bf16.h>
#include <math_constants.h>

#define B_  4
#define S_  4096
#define D_  256
#define H_  4
#define DH_ 64
#define MT_ (B_ * S_)
#define BH_ (B_ * H_)

typedef unsigned int       u32;
typedef unsigned long long u64;

// ---------------------------------------------------------------------------
// Scratch: Q/K/V stored as packed bf16 pairs (u32 = {hi:odd col, lo:even col}),
// split into hi/lo mantissa halves. Layout [bh][s][dh/2].
// ---------------------------------------------------------------------------
#define QKV_WORDS ((size_t)BH_ * S_ * (DH_ / 2))
__device__ u32 g_Qh[QKV_WORDS];
__device__ u32 g_Ql[QKV_WORDS];
__device__ u32 g_Kh[QKV_WORDS];
__device__ u32 g_Kl[QKV_WORDS];
__device__ u32 g_Vh[QKV_WORDS];
__device__ u32 g_Vl[QKV_WORDS];
__device__ float g_attn[(size_t)B_ * S_ * D_];

// ---------------------------------------------------------------------------
// PTX helpers (baseline PTX only — no sm_103a-gated features)
// ---------------------------------------------------------------------------
__device__ __forceinline__ u32 smem_u32(const void* p) {
    u32 a;
    asm("{ .reg .u64 t; cvta.to.shared.u64 t, %1; cvt.u32.u64 %0, t; }"
        : "=r"(a) : "l"(p));
    return a;
}
// pack: {hi16 = bf16(a), lo16 = bf16(b)}
__device__ __forceinline__ u32 cvt2(float a, float b) {
    u32 r;
    asm("cvt.rn.bf16x2.f32 %0, %1, %2;" : "=r"(r) : "f"(a), "f"(b));
    return r;
}
__device__ __forceinline__ float bflo(u32 w) { return __uint_as_float(w << 16); }
__device__ __forceinline__ float bfhi(u32 w) { return __uint_as_float(w & 0xffff0000u); }

__device__ __forceinline__ void mma_bf16(float c[4], u32 a0, u32 a1, u32 a2, u32 a3,
                                         u32 b0, u32 b1) {
    asm volatile(
        "mma.sync.aligned.m16n8k16.row.col.f32.bf16.bf16.f32 "
        "{%0,%1,%2,%3},{%4,%5,%6,%7},{%8,%9},{%0,%1,%2,%3};"
        : "+f"(c[0]), "+f"(c[1]), "+f"(c[2]), "+f"(c[3])
        : "r"(a0), "r"(a1), "r"(a2), "r"(a3), "r"(b0), "r"(b1));
}
#define LDSM_X4(r0, r1, r2, r3, a) \
    asm volatile("ldmatrix.sync.aligned.m8n8.x4.shared.b16 {%0,%1,%2,%3}, [%4];" \
                 : "=r"(r0), "=r"(r1), "=r"(r2), "=r"(r3) : "r"(a))
#define LDSM_X4T(r0, r1, r2, r3, a) \
    asm volatile("ldmatrix.sync.aligned.m8n8.x4.trans.shared.b16 {%0,%1,%2,%3}, [%4];" \
                 : "=r"(r0), "=r"(r1), "=r"(r2), "=r"(r3) : "r"(a))

__device__ __forceinline__ void cp16(u32 dst, const void* src) {
    asm volatile("cp.async.cg.shared.global [%0], [%1], 16;" :: "r"(dst), "l"(src));
}
#define CP_COMMIT() asm volatile("cp.async.commit_group;" ::: "memory")
#define CP_WAIT(n)  asm volatile("cp.async.wait_group %0;" :: "n"(n) : "memory")

// XOR swizzle: row stride 128B, 16B chunk c -> physical chunk c ^ (row & 7)
__device__ __forceinline__ u32 swz(int row, int chunk) {
    return (u32)(row * 128 + (((chunk ^ row) & 7) << 4));
}

// ---------------------------------------------------------------------------
// Flash attention: 4 warps x 16 q-rows = 64 q-rows/CTA. grid (S/64, BH).
// smem: Qh/Ql stage 16KB + 2 x (Kh,Kl,Vh,Vl = 32KB) double buffer = 80KB.
// ---------------------------------------------------------------------------
#define SQ_OFF    0
#define BUF_OFF   16384
#define BUF_STRIDE 32768
#define ATTN_SMEM (16384 + 2 * 32768)

__global__ void __launch_bounds__(128) attn_kernel()
{
    extern __shared__ char sm[];
    const u32 sb  = smem_u32(sm);
    const int tid = threadIdx.x;
    const int w   = tid >> 5;
    const int L   = tid & 31;
    const int bh  = blockIdx.y;
    const int q0  = blockIdx.x * 64;

    const size_t head = (size_t)bh * S_ * (DH_ / 2);
    const u32* Qh = g_Qh + head; const u32* Ql = g_Ql + head;
    const u32* Kh = g_Kh + head; const u32* Kl = g_Kl + head;
    const u32* Vh = g_Vh + head; const u32* Vl = g_Vl + head;

    // lane constants for ldmatrix addressing
    const int rt = L & 7;
    const int lb = (L >> 3) & 1;
    const int lc = L >> 4;

    // ---- prologue: async Q stage + first two K/V tiles ----
    {   // Q: 2 matrices x 512 chunks of 16B (4 u32)
        #pragma unroll
        for (int i = 0; i < 4; i++) {
            int idx = tid + i * 128;           // < 512
            int r = idx >> 3, c = idx & 7;
            cp16(sb + SQ_OFF + swz(r, c),        Qh + (size_t)(q0 + r) * 32 + c * 4);
            cp16(sb + SQ_OFF + 8192 + swz(r, c), Ql + (size_t)(q0 + r) * 32 + c * 4);
        }
        CP_COMMIT();
    }
    const u32* kvsrc[4] = {Kh, Kl, Vh, Vl};
    #pragma unroll
    for (int t0 = 0; t0 < 2; t0++) {
        u32 bufb = sb + BUF_OFF + t0 * BUF_STRIDE;
        #pragma unroll
        for (int m = 0; m < 4; m++)
            #pragma unroll
            for (int i = 0; i < 4; i++) {
                int idx = tid + i * 128;
                int r = idx >> 3, c = idx & 7;
                cp16(bufb + m * 8192 + swz(r, c),
                     kvsrc[m] + (size_t)(t0 * 64 + r) * 32 + c * 4);
            }
        CP_COMMIT();
    }

    CP_WAIT(2);          // Q group complete
    __syncthreads();

    // ---- Q fragments (persist whole loop) ----
    u32 qh[4][4], ql[4][4];
    #pragma unroll
    for (int j = 0; j < 4; j++) {
        int row = w * 16 + rt + lb * 8;
        u32 a = sb + SQ_OFF + swz(row, 2 * j + lc);
        LDSM_X4(qh[j][0], qh[j][1], qh[j][2], qh[j][3], a);
        u32 al = sb + SQ_OFF + 8192 + swz(row, 2 * j + lc);
        LDSM_X4(ql[j][0], ql[j][1], ql[j][2], ql[j][3], al);
    }

    float oacc[8][4];
    #pragma unroll
    for (int t = 0; t < 8; t++)
        #pragma unroll
        for (int e = 0; e < 4; e++) oacc[t][e] = 0.0f;
    float m_lo = -CUDART_INF_F, m_hi = -CUDART_INF_F;
    float l_lo = 0.0f, l_hi = 0.0f;

    const int NT = S_ / 64;
    for (int it = 0; it < NT; it++) {
        CP_WAIT(1);
        __syncthreads();
        const u32 bufb = sb + BUF_OFF + (it & 1) * BUF_STRIDE;
        const u32 aKH = bufb, aKL = bufb + 8192;
        const u32 aVH = bufb + 16384, aVL = bufb + 24576;

        // ---- S = Q K^T (3-split) ----
        float sacc[8][4];
        #pragma unroll
        for (int t = 0; t < 8; t++)
            #pragma unroll
            for (int e = 0; e < 4; e++) sacc[t][e] = 0.0f;

        #pragma unroll
        for (int j = 0; j < 4; j++) {
            #pragma unroll
            for (int p = 0; p < 4; p++) {   // n-tile pair {2p, 2p+1}
                int row = 16 * p + rt + lc * 8;
                int ch  = 2 * j + lb;
                u32 kh0, kh1, kh2, kh3, kl0, kl1, kl2, kl3;
                LDSM_X4(kh0, kh1, kh2, kh3, aKH + swz(row, ch));
                LDSM_X4(kl0, kl1, kl2, kl3, aKL + swz(row, ch));
                mma_bf16(sacc[2*p],   qh[j][0], qh[j][1], qh[j][2], qh[j][3], kh0, kh1);
                mma_bf16(sacc[2*p],   ql[j][0], ql[j][1], ql[j][2], ql[j][3], kh0, kh1);
                mma_bf16(sacc[2*p],   qh[j][0], qh[j][1], qh[j][2], qh[j][3], kl0, kl1);
                mma_bf16(sacc[2*p+1], qh[j][0], qh[j][1], qh[j][2], qh[j][3], kh2, kh3);
                mma_bf16(sacc[2*p+1], ql[j][0], ql[j][1], ql[j][2], ql[j][3], kh2, kh3);
                mma_bf16(sacc[2*p+1], qh[j][0], qh[j][1], qh[j][2], qh[j][3], kl2, kl3);
            }
        }

        // ---- online softmax (rows: T/4 and T/4+8; 4 lanes share a row) ----
        float mlo = -CUDART_INF_F, mhi = -CUDART_INF_F;
        #pragma unroll
        for (int t = 0; t < 8; t++) {
            mlo = fmaxf(mlo, fmaxf(sacc[t][0], sacc[t][1]));
            mhi = fmaxf(mhi, fmaxf(sacc[t][2], sacc[t][3]));
        }
        mlo = fmaxf(mlo, __shfl_xor_sync(0xffffffffu, mlo, 1));
        mlo = fmaxf(mlo, __shfl_xor_sync(0xffffffffu, mlo, 2));
        mhi = fmaxf(mhi, __shfl_xor_sync(0xffffffffu, mhi, 1));
        mhi = fmaxf(mhi, __shfl_xor_sync(0xffffffffu, mhi, 2));

        float mnlo = fmaxf(m_lo, mlo), mnhi = fmaxf(m_hi, mhi);
        float clo = __expf(m_lo - mnlo), chi = __expf(m_hi - mnhi);
        m_lo = mnlo; m_hi = mnhi;

        u32 ph[8][2], pl[8][2];
        float alo = 0.0f, ahi = 0.0f;
        #pragma unroll
        for (int t = 0; t < 8; t++) {
            float p0 = __expf(sacc[t][0] - mnlo);
            float p1 = __expf(sacc[t][1] - mnlo);
            float p2 = __expf(sacc[t][2] - mnhi);
            float p3 = __expf(sacc[t][3] - mnhi);
            alo += p0 + p1; ahi += p2 + p3;
            u32 h0 = cvt2(p1, p0), h1 = cvt2(p3, p2);
            ph[t][0] = h0; ph[t][1] = h1;
            pl[t][0] = cvt2(p1 - bfhi(h0), p0 - bflo(h0));
            pl[t][1] = cvt2(p3 - bfhi(h1), p2 - bflo(h1));
        }
        l_lo = l_lo * clo + alo;
        l_hi = l_hi * chi + ahi;

        #pragma unroll
        for (int t = 0; t < 8; t++) {
            oacc[t][0] *= clo; oacc[t][1] *= clo;
            oacc[t][2] *= chi; oacc[t][3] *= chi;
        }

        // ---- O += P V (3-split, V via ldmatrix.trans) ----
        #pragma unroll
        for (int j = 0; j < 4; j++) {
            u32 ah0 = ph[2*j][0],   ah1 = ph[2*j][1];
            u32 ah2 = ph[2*j+1][0], ah3 = ph[2*j+1][1];
            u32 al0 = pl[2*j][0],   al1 = pl[2*j][1];
            u32 al2 = pl[2*j+1][0], al3 = pl[2*j+1][1];
            int row = 16 * j + rt + lb * 8;
            #pragma unroll
            for (int t = 0; t < 4; t++) {   // n-tile pair {2t, 2t+1}
                int ch = 2 * t + lc;
                u32 vh0, vh1, vh2, vh3, vl0, vl1, vl2, vl3;
                LDSM_X4T(vh0, vh1, vh2, vh3, aVH + swz(row, ch));
                LDSM_X4T(vl0, vl1, vl2, vl3, aVL + swz(row, ch));
                mma_bf16(oacc[2*t],   ah0, ah1, ah2, ah3, vh0, vh1);
                mma_bf16(oacc[2*t],   al0, al1, al2, al3, vh0, vh1);
                mma_bf16(oacc[2*t],   ah0, ah1, ah2, ah3, vl0, vl1);
                mma_bf16(oacc[2*t+1], ah0, ah1, ah2, ah3, vh2, vh3);
                mma_bf16(oacc[2*t+1], al0, al1, al2, al3, vh2, vh3);
                mma_bf16(oacc[2*t+1], ah0, ah1, ah2, ah3, vl2, vl3);
            }
        }

        __syncthreads();   // buffer fully consumed
        if (it + 2 < NT) {
            u32 bb2 = sb + BUF_OFF + (it & 1) * BUF_STRIDE;
            int j2 = (it + 2) * 64;
            #pragma unroll
            for (int m = 0; m < 4; m++)
                #pragma unroll
                for (int i = 0; i < 4; i++) {
                    int idx = tid + i * 128;
                    int r = idx >> 3, c = idx & 7;
                    cp16(bb2 + m * 8192 + swz(r, c),
                         kvsrc[m] + (size_t)(j2 + r) * 32 + c * 4);
                }
        }
        CP_COMMIT();
    }

    // ---- epilogue ----
    float llo = l_lo + __shfl_xor_sync(0xffffffffu, l_lo, 1);
    llo += __shfl_xor_sync(0xffffffffu, llo, 2);
    float lhi = l_hi + __shfl_xor_sync(0xffffffffu, l_hi, 1);
    lhi += __shfl_xor_sync(0xffffffffu, lhi, 2);
    const float ilo = 1.0f / llo, ihi = 1.0f / lhi;

    const int bb = bh >> 2, h = bh & 3;
    const int rlo = q0 + w * 16 + (L >> 2);
    const int colb = h * DH_ + (L & 3) * 2;
    #pragma unroll
    for (int t = 0; t < 8; t++) {
        float2 v0; v0.x = oacc[t][0] * ilo; v0.y = oacc[t][1] * ilo;
        float2 v1; v1.x = oacc[t][2] * ihi; v1.y = oacc[t][3] * ihi;
        *(float2*)&g_attn[(size_t)(bb * S_ + rlo)     * D_ + colb + 8 * t] = v0;
        *(float2*)&g_attn[(size_t)(bb * S_ + rlo + 8) * D_ + colb + 8 * t] = v1;
    }
}

// ---------------------------------------------------------------------------
// Kernel 1: fused QKV projection (R1 scalar core), epilogue emits split bf16.
// ---------------------------------------------------------------------------
__global__ void __launch_bounds__(256) qkv_gemm(
    const float* __restrict__ X,
    const float* __restrict__ Wq, const float* __restrict__ bq,
    const float* __restrict__ Wk, const float* __restrict__ bk,
    const float* __restrict__ Wv, const float* __restrict__ bv)
{
    __shared__ float Xt[32][68];
    __shared__ float Ws[32][68];

    const float* W; const float* bias; u32* oh; u32* ol; float qscale;
    if (blockIdx.z == 0)      { W = Wq; bias = bq; oh = g_Qh; ol = g_Ql; qscale = 0.125f; }
    else if (blockIdx.z == 1) { W = Wk; bias = bk; oh = g_Kh; ol = g_Kl; qscale = 1.0f;   }
    else                      { W = Wv; bias = bv; oh = g_Vh; ol = g_Vl; qscale = 1.0f;   }

    const int m0 = blockIdx.x * 64;
    const int h  = blockIdx.y;
    const int n0 = h * 64;
    const int tid = threadIdx.x;
    const int tx = tid & 15, ty = tid >> 4;

    float acc[4][4] = {};

    for (int kk = 0; kk < D_; kk += 32) {
        #pragma unroll
        for (int it = 0; it < 8; it++) {
            int idx = tid + it * 256;
            {
                int r = idx >> 5, k = idx & 31;
                Xt[k][r] = X[(size_t)(m0 + r) * D_ + kk + k];
            }
            {
                int k = idx >> 6, n = idx & 63;
                Ws[k][n] = W[(size_t)(kk + k) * D_ + n0 + n];
            }
        }
        __syncthreads();
        #pragma unroll
        for (int k = 0; k < 32; k++) {
            float4 a4 = *(const float4*)&Xt[k][ty * 4];
            float4 b4 = *(const float4*)&Ws[k][tx * 4];
            float av[4] = {a4.x, a4.y, a4.z, a4.w};
            float bw[4] = {b4.x, b4.y, b4.z, b4.w};
            #pragma unroll
            for (int i = 0; i < 4; i++)
                #pragma unroll
                for (int j = 0; j < 4; j++)
                    acc[i][j] = fmaf(av[i], bw[j], acc[i][j]);
        }
        __syncthreads();
    }

    const int bb = m0 >> 12;
    const int sbase = m0 & (S_ - 1);
    #pragma unroll
    for (int i = 0; i < 4; i++) {
        const int s = sbase + ty * 4 + i;
        const size_t rowb = ((size_t)(bb * H_ + h) * S_ + s) * 32 + tx * 2;
        float v[4];
        #pragma unroll
        for (int j = 0; j < 4; j++)
            v[j] = (acc[i][j] + bias[n0 + tx * 4 + j]) * qscale;
        u32 h0 = cvt2(v[1], v[0]);
        u32 h1 = cvt2(v[3], v[2]);
        oh[rowb]     = h0;
        oh[rowb + 1] = h1;
        ol[rowb]     = cvt2(v[1] - bfhi(h0), v[0] - bflo(h0));
        ol[rowb + 1] = cvt2(v[3] - bfhi(h1), v[2] - bflo(h1));
    }
}

// ---------------------------------------------------------------------------
// Kernel 3: output projection (R1 scalar, unchanged).
// ---------------------------------------------------------------------------
__global__ void __launch_bounds__(256) out_gemm(
    const float* __restrict__ Wo, const float* __restrict__ bo,
    float* __restrict__ out)
{
    __shared__ float Xt[32][68];
    __shared__ float Ws[32][68];

    const int m0 = blockIdx.x * 64;
    const int n0 = blockIdx.y * 64;
    const int tid = threadIdx.x;
    const int tx = tid & 15, ty = tid >> 4;

    float acc[4][4] = {};

    for (int kk = 0; kk < D_; kk += 32) {
        #pragma unroll
        for (int it = 0; it < 8; it++) {
            int idx = tid + it * 256;
            {
                int r = idx >> 5, k = idx & 31;
                Xt[k][r] = g_attn[(size_t)(m0 + r) * D_ + kk + k];
            }
            {
                int k = idx >> 6, n = idx & 63;
                Ws[k][n] = Wo[(size_t)(kk + k) * D_ + n0 + n];
            }
        }
        __syncthreads();
        #pragma unroll
        for (int k = 0; k < 32; k++) {
            float4 a4 = *(const float4*)&Xt[k][ty * 4];
            float4 b4 = *(const float4*)&Ws[k][tx * 4];
            float av[4] = {a4.x, a4.y, a4.z, a4.w};
            float bw[4] = {b4.x, b4.y, b4.z, b4.w};
            #pragma unroll
            for (int i = 0; i < 4; i++)
                #pragma unroll
                for (int j = 0; j < 4; j++)
                    acc[i][j] = fmaf(av[i], bw[j], acc[i][j]);
        }
        __syncthreads();
    }

    #pragma unroll
    for (int i = 0; i < 4; i++)
        #pragma unroll
        for (int j = 0; j < 4; j++)
            out[(size_t)(m0 + ty * 4 + i) * D_ + n0 + tx * 4 + j] =
                acc[i][j] + bo[n0 + tx * 4 + j];
}

// ---------------------------------------------------------------------------
// Launch
// ---------------------------------------------------------------------------
extern "C" void kernel_launch(void* const* d_in, const int* in_sizes, int n_in,
                              void* d_out, int out_size)
{
    const float* X  = (const float*)d_in[0];
    const float* Wq = (const float*)d_in[1];
    const float* bq = (const float*)d_in[2];
    const float* Wk = (const float*)d_in[3];
    const float* bk = (const float*)d_in[4];
    const float* Wv = (const float*)d_in[5];
    const float* bv = (const float*)d_in[6];
    const float* Wo = (const float*)d_in[7];
    const float* bo = (const float*)d_in[8];
    float* out = (float*)d_out;

    cudaFuncSetAttribute(attn_kernel,
                         cudaFuncAttributeMaxDynamicSharedMemorySize,
                         ATTN_SMEM);

    qkv_gemm<<<dim3(MT_ / 64, H_, 3), 256>>>(X, Wq, bq, Wk, bk, Wv, bv);
    attn_kernel<<<dim3(S_ / 64, BH_), 128, ATTN_SMEM>>>();
    out_gemm<<<dim3(MT_ / 64, D_ / 64), 256>>>(Wo, bo, out);
}

// round 5
// speedup vs baseline: 5.0770x; 1.2876x over previous
#include <cuda_runtime.h>
#include <cuda_bf16.h>
#include <math_constants.h>

#define B_  4
#define S_  4096
#define D_  256
#define H_  4
#define DH_ 64
#define MT_ (B_ * S_)
#define BH_ (B_ * H_)
#define LOG2E 1.4426950408889634f

typedef unsigned int       u32;
typedef unsigned long long u64;

// ---------------------------------------------------------------------------
// Scratch: everything bf16 hi/lo split, packed u32 = {hi16: odd col, lo16: even}
// ---------------------------------------------------------------------------
#define QKV_WORDS ((size_t)BH_ * S_ * (DH_ / 2))
#define ROW_WORDS (D_ / 2)                       // 128 words per 256-wide row
__device__ u32 g_Qh[QKV_WORDS];  __device__ u32 g_Ql[QKV_WORDS];
__device__ u32 g_Kh[QKV_WORDS];  __device__ u32 g_Kl[QKV_WORDS];
__device__ u32 g_Vh[QKV_WORDS];  __device__ u32 g_Vl[QKV_WORDS];
__device__ u32 g_Xh[(size_t)MT_ * ROW_WORDS];    // input split
__device__ u32 g_Xl[(size_t)MT_ * ROW_WORDS];
__device__ u32 g_Ah[(size_t)MT_ * ROW_WORDS];    // attention output split
__device__ u32 g_Al[(size_t)MT_ * ROW_WORDS];
__device__ u32 g_Wth[4 * 256 * ROW_WORDS];       // W^T split: [z][n][k/2]
__device__ u32 g_Wtl[4 * 256 * ROW_WORDS];

// ---------------------------------------------------------------------------
// PTX helpers (baseline PTX only)
// ---------------------------------------------------------------------------
__device__ __forceinline__ u32 smem_u32(const void* p) {
    u32 a;
    asm("{ .reg .u64 t; cvta.to.shared.u64 t, %1; cvt.u32.u64 %0, t; }"
        : "=r"(a) : "l"(p));
    return a;
}
__device__ __forceinline__ u32 cvt2(float a, float b) {   // {hi=bf16(a), lo=bf16(b)}
    u32 r;
    asm("cvt.rn.bf16x2.f32 %0, %1, %2;" : "=r"(r) : "f"(a), "f"(b));
    return r;
}
__device__ __forceinline__ float bflo(u32 w) { return __uint_as_float(w << 16); }
__device__ __forceinline__ float bfhi(u32 w) { return __uint_as_float(w & 0xffff0000u); }
__device__ __forceinline__ float ex2f(float x) {
    float y; asm("ex2.approx.f32 %0, %1;" : "=f"(y) : "f"(x)); return y;
}
__device__ __forceinline__ void mma_bf16(float c[4], const u32 a[4], u32 b0, u32 b1) {
    asm volatile(
        "mma.sync.aligned.m16n8k16.row.col.f32.bf16.bf16.f32 "
        "{%0,%1,%2,%3},{%4,%5,%6,%7},{%8,%9},{%0,%1,%2,%3};"
        : "+f"(c[0]), "+f"(c[1]), "+f"(c[2]), "+f"(c[3])
        : "r"(a[0]), "r"(a[1]), "r"(a[2]), "r"(a[3]), "r"(b0), "r"(b1));
}
#define LDSM_X4(r0, r1, r2, r3, a) \
    asm volatile("ldmatrix.sync.aligned.m8n8.x4.shared.b16 {%0,%1,%2,%3}, [%4];" \
                 : "=r"(r0), "=r"(r1), "=r"(r2), "=r"(r3) : "r"(a))
#define LDSM_A(fr, a) LDSM_X4(fr[0], fr[1], fr[2], fr[3], a)
#define LDSM_X4T(r0, r1, r2, r3, a) \
    asm volatile("ldmatrix.sync.aligned.m8n8.x4.trans.shared.b16 {%0,%1,%2,%3}, [%4];" \
                 : "=r"(r0), "=r"(r1), "=r"(r2), "=r"(r3) : "r"(a))
__device__ __forceinline__ void cp16(u32 dst, const void* src) {
    asm volatile("cp.async.cg.shared.global [%0], [%1], 16;" :: "r"(dst), "l"(src));
}
#define CP_COMMIT() asm volatile("cp.async.commit_group;" ::: "memory")
#define CP_WAIT(n)  asm volatile("cp.async.wait_group %0;" :: "n"(n) : "memory")

__device__ __forceinline__ u32 swz(int row, int chunk) {
    return (u32)(row * 128 + (((chunk ^ row) & 7) << 4));
}

// ---------------------------------------------------------------------------
// Kernel 0: prep — split X into bf16 hi/lo; transpose+split W matrices.
// ---------------------------------------------------------------------------
#define XWORDS (2097152)     // 16384 * 128
#define WWORDS (131072)      // 4 * 256 * 128
__global__ void __launch_bounds__(256) prep_kernel(
    const float* __restrict__ X,
    const float* __restrict__ Wq, const float* __restrict__ Wk,
    const float* __restrict__ Wv, const float* __restrict__ Wo)
{
    const int w = blockIdx.x * 256 + threadIdx.x;
    if (w < XWORDS) {
        float2 f = ((const float2*)X)[w];
        u32 hi = cvt2(f.y, f.x);
        g_Xh[w] = hi;
        g_Xl[w] = cvt2(f.y - bfhi(hi), f.x - bflo(hi));
    } else if (w < XWORDS + WWORDS) {
        int u = w - XWORDS;
        int z = u >> 15, r = u & 32767;
        int n = r >> 7, kp = r & 127;
        const float* Wm = (z == 0) ? Wq : (z == 1) ? Wk : (z == 2) ? Wv : Wo;
        float f0 = Wm[(size_t)(2 * kp)     * 256 + n];
        float f1 = Wm[(size_t)(2 * kp + 1) * 256 + n];
        u32 hi = cvt2(f1, f0);
        g_Wth[u] = hi;
        g_Wtl[u] = cvt2(f1 - bfhi(hi), f0 - bflo(hi));
    }
}

// ---------------------------------------------------------------------------
// HMMA GEMM core used by qkv and out kernels.
// CTA: 128 threads (4 warps), tile M=128 x N=64, K=256 in 4 blocks of 64.
// smem/buffer: AH 16K | AL 16K | BH 8K | BL 8K = 48KB, double buffered (96KB).
// ---------------------------------------------------------------------------
#define GB_AH 0
#define GB_AL 16384
#define GB_BH 32768
#define GB_BL 40960
#define GBUF  49152
#define GEMM_SMEM (2 * GBUF)

__device__ __forceinline__ void gemm_stage(u32 sb, int bufi, int kb,
                                           const u32* Ah, const u32* Al,
                                           const u32* Bh, const u32* Bl,
                                           int m0, int n0, int tid)
{
    const u32 bufb = sb + bufi * GBUF;
    #pragma unroll
    for (int i = 0; i < 8; i++) {
        int idx = tid + i * 128;           // < 1024
        int r = idx >> 3, c = idx & 7;
        const size_t go = (size_t)(m0 + r) * ROW_WORDS + kb * 32 + c * 4;
        cp16(bufb + GB_AH + swz(r, c), Ah + go);
        cp16(bufb + GB_AL + swz(r, c), Al + go);
    }
    #pragma unroll
    for (int i = 0; i < 4; i++) {
        int idx = tid + i * 128;           // < 512
        int r = idx >> 3, c = idx & 7;
        const size_t go = (size_t)(n0 + r) * ROW_WORDS + kb * 32 + c * 4;
        cp16(bufb + GB_BH + swz(r, c), Bh + go);
        cp16(bufb + GB_BL + swz(r, c), Bl + go);
    }
}

// computes acc[mt][t][e] for this warp; acc must be zeroed by caller
__device__ __forceinline__ void gemm_main(u32 sb, float acc[2][8][4],
                                          const u32* Ah, const u32* Al,
                                          const u32* Bh, const u32* Bl,
                                          int m0, int n0, int tid)
{
    const int w  = tid >> 5;
    const int L  = tid & 31;
    const int rt = L & 7;
    const int lb = (L >> 3) & 1;
    const int lc = L >> 4;

    gemm_stage(sb, 0, 0, Ah, Al, Bh, Bl, m0, n0, tid);
    CP_COMMIT();
    gemm_stage(sb, 1, 1, Ah, Al, Bh, Bl, m0, n0, tid);
    CP_COMMIT();

    for (int kb = 0; kb < 4; kb++) {
        CP_WAIT(1);
        __syncthreads();
        const u32 bufb = sb + (kb & 1) * GBUF;
        const u32 aAH = bufb + GB_AH, aAL = bufb + GB_AL;
        const u32 aBH = bufb + GB_BH, aBL = bufb + GB_BL;

        #pragma unroll
        for (int j = 0; j < 4; j++) {
            u32 ah[2][4], al[2][4];
            #pragma unroll
            for (int mt = 0; mt < 2; mt++) {
                int row = w * 32 + mt * 16 + rt + lb * 8;
                LDSM_A(ah[mt], aAH + swz(row, 2 * j + lc));
                LDSM_A(al[mt], aAL + swz(row, 2 * j + lc));
            }
            #pragma unroll
            for (int p = 0; p < 4; p++) {
                int row = 16 * p + rt + lc * 8;
                int ch  = 2 * j + lb;
                u32 bh0, bh1, bh2, bh3, bl0, bl1, bl2, bl3;
                LDSM_X4(bh0, bh1, bh2, bh3, aBH + swz(row, ch));
                LDSM_X4(bl0, bl1, bl2, bl3, aBL + swz(row, ch));
                #pragma unroll
                for (int mt = 0; mt < 2; mt++) {
                    mma_bf16(acc[mt][2*p],   ah[mt], bh0, bh1);
                    mma_bf16(acc[mt][2*p],   al[mt], bh0, bh1);
                    mma_bf16(acc[mt][2*p],   ah[mt], bl0, bl1);
                    mma_bf16(acc[mt][2*p+1], ah[mt], bh2, bh3);
                    mma_bf16(acc[mt][2*p+1], al[mt], bh2, bh3);
                    mma_bf16(acc[mt][2*p+1], ah[mt], bl2, bl3);
                }
            }
        }
        __syncthreads();
        if (kb + 2 < 4)
            gemm_stage(sb, kb & 1, kb + 2, Ah, Al, Bh, Bl, m0, n0, tid);
        CP_COMMIT();
    }
}

// ---------------------------------------------------------------------------
// Kernel 1: QKV projection via HMMA. grid (MT/128, H, 3), block 128.
// Writes split bf16 head layout [bh][s][dh/2]; Q scaled by log2e/8.
// ---------------------------------------------------------------------------
__global__ void __launch_bounds__(128) qkv_hmma(
    const float* __restrict__ bq, const float* __restrict__ bk,
    const float* __restrict__ bv)
{
    extern __shared__ char sm[];
    const u32 sb  = smem_u32(sm);
    const int tid = threadIdx.x;
    const int z   = blockIdx.z;
    const int h   = blockIdx.y;
    const int m0  = blockIdx.x * 128;
    const int n0  = h * 64;

    const float* bias = (z == 0) ? bq : (z == 1) ? bk : bv;
    u32* oh = (z == 0) ? g_Qh : (z == 1) ? g_Kh : g_Vh;
    u32* ol = (z == 0) ? g_Ql : (z == 1) ? g_Kl : g_Vl;
    const float qs = (z == 0) ? (0.125f * LOG2E) : 1.0f;

    float acc[2][8][4];
    #pragma unroll
    for (int mt = 0; mt < 2; mt++)
        #pragma unroll
        for (int t = 0; t < 8; t++)
            #pragma unroll
            for (int e = 0; e < 4; e++) acc[mt][t][e] = 0.0f;

    gemm_main(sb, acc, g_Xh, g_Xl,
              g_Wth + (size_t)z * 256 * ROW_WORDS,
              g_Wtl + (size_t)z * 256 * ROW_WORDS, m0, n0, tid);

    // epilogue
    const int w  = tid >> 5;
    const int L  = tid & 31;
    const int lr = L >> 2, lcq = L & 3;
    float b2[8][2];
    #pragma unroll
    for (int t = 0; t < 8; t++) {
        b2[t][0] = bias[n0 + 8 * t + lcq * 2];
        b2[t][1] = bias[n0 + 8 * t + lcq * 2 + 1];
    }
    const int bb = m0 >> 12;
    const int sbase = m0 & (S_ - 1);
    #pragma unroll
    for (int mt = 0; mt < 2; mt++) {
        #pragma unroll
        for (int half = 0; half < 2; half++) {
            int s = sbase + w * 32 + mt * 16 + lr + half * 8;
            size_t rw = ((size_t)(bb * H_ + h) * S_ + s) * 32 + lcq;
            #pragma unroll
            for (int t = 0; t < 8; t++) {
                float v0 = (acc[mt][t][half * 2 + 0] + b2[t][0]) * qs;
                float v1 = (acc[mt][t][half * 2 + 1] + b2[t][1]) * qs;
                u32 hi = cvt2(v1, v0);
                oh[rw + 4 * t] = hi;
                ol[rw + 4 * t] = cvt2(v1 - bfhi(hi), v0 - bflo(hi));
            }
        }
    }
}

// ---------------------------------------------------------------------------
// Kernel 3: output projection via HMMA. grid (MT/128, 4), block 128. fp32 out.
// ---------------------------------------------------------------------------
__global__ void __launch_bounds__(128) out_hmma(
    const float* __restrict__ bo, float* __restrict__ out)
{
    extern __shared__ char sm[];
    const u32 sb  = smem_u32(sm);
    const int tid = threadIdx.x;
    const int m0  = blockIdx.x * 128;
    const int n0  = blockIdx.y * 64;

    float acc[2][8][4];
    #pragma unroll
    for (int mt = 0; mt < 2; mt++)
        #pragma unroll
        for (int t = 0; t < 8; t++)
            #pragma unroll
            for (int e = 0; e < 4; e++) acc[mt][t][e] = 0.0f;

    gemm_main(sb, acc, g_Ah, g_Al,
              g_Wth + (size_t)3 * 256 * ROW_WORDS,
              g_Wtl + (size_t)3 * 256 * ROW_WORDS, m0, n0, tid);

    const int w  = tid >> 5;
    const int L  = tid & 31;
    const int lr = L >> 2, lcq = L & 3;
    float b2[8][2];
    #pragma unroll
    for (int t = 0; t < 8; t++) {
        b2[t][0] = bo[n0 + 8 * t + lcq * 2];
        b2[t][1] = bo[n0 + 8 * t + lcq * 2 + 1];
    }
    #pragma unroll
    for (int mt = 0; mt < 2; mt++) {
        #pragma unroll
        for (int half = 0; half < 2; half++) {
            int m = m0 + w * 32 + mt * 16 + lr + half * 8;
            float* orow = out + (size_t)m * D_ + n0 + lcq * 2;
            #pragma unroll
            for (int t = 0; t < 8; t++) {
                float2 v;
                v.x = acc[mt][t][half * 2 + 0] + b2[t][0];
                v.y = acc[mt][t][half * 2 + 1] + b2[t][1];
                *(float2*)&orow[8 * t] = v;
            }
        }
    }
}

// ---------------------------------------------------------------------------
// Kernel 2: flash attention (R4 core, exp2 domain, split-bf16 output).
// grid (S/64, BH), block 128.
// ---------------------------------------------------------------------------
#define SQ_OFF     0
#define BUF_OFF    16384
#define BUF_STRIDE 32768
#define ATTN_SMEM (16384 + 2 * 32768)

__global__ void __launch_bounds__(128) attn_kernel()
{
    extern __shared__ char sm[];
    const u32 sb  = smem_u32(sm);
    const int tid = threadIdx.x;
    const int w   = tid >> 5;
    const int L   = tid & 31;
    const int bh  = blockIdx.y;
    const int q0  = blockIdx.x * 64;

    const size_t head = (size_t)bh * S_ * (DH_ / 2);
    const u32* Qh = g_Qh + head; const u32* Ql = g_Ql + head;
    const u32* Kh = g_Kh + head; const u32* Kl = g_Kl + head;
    const u32* Vh = g_Vh + head; const u32* Vl = g_Vl + head;

    const int rt = L & 7;
    const int lb = (L >> 3) & 1;
    const int lc = L >> 4;

    {   // Q stage
        #pragma unroll
        for (int i = 0; i < 4; i++) {
            int idx = tid + i * 128;
            int r = idx >> 3, c = idx & 7;
            cp16(sb + SQ_OFF + swz(r, c),        Qh + (size_t)(q0 + r) * 32 + c * 4);
            cp16(sb + SQ_OFF + 8192 + swz(r, c), Ql + (size_t)(q0 + r) * 32 + c * 4);
        }
        CP_COMMIT();
    }
    const u32* kvsrc[4] = {Kh, Kl, Vh, Vl};
    #pragma unroll
    for (int t0 = 0; t0 < 2; t0++) {
        u32 bufb = sb + BUF_OFF + t0 * BUF_STRIDE;
        #pragma unroll
        for (int m = 0; m < 4; m++)
            #pragma unroll
            for (int i = 0; i < 4; i++) {
                int idx = tid + i * 128;
                int r = idx >> 3, c = idx & 7;
                cp16(bufb + m * 8192 + swz(r, c),
                     kvsrc[m] + (size_t)(t0 * 64 + r) * 32 + c * 4);
            }
        CP_COMMIT();
    }

    CP_WAIT(2);
    __syncthreads();

    u32 qh[4][4], ql[4][4];
    #pragma unroll
    for (int j = 0; j < 4; j++) {
        int row = w * 16 + rt + lb * 8;
        LDSM_A(qh[j], sb + SQ_OFF + swz(row, 2 * j + lc));
        LDSM_A(ql[j], sb + SQ_OFF + 8192 + swz(row, 2 * j + lc));
    }

    float oacc[8][4];
    #pragma unroll
    for (int t = 0; t < 8; t++)
        #pragma unroll
        for (int e = 0; e < 4; e++) oacc[t][e] = 0.0f;
    float m_lo = -CUDART_INF_F, m_hi = -CUDART_INF_F;
    float l_lo = 0.0f, l_hi = 0.0f;

    const int NT = S_ / 64;
    for (int it = 0; it < NT; it++) {
        CP_WAIT(1);
        __syncthreads();
        const u32 bufb = sb + BUF_OFF + (it & 1) * BUF_STRIDE;
        const u32 aKH = bufb, aKL = bufb + 8192;
        const u32 aVH = bufb + 16384, aVL = bufb + 24576;

        float sacc[8][4];
        #pragma unroll
        for (int t = 0; t < 8; t++)
            #pragma unroll
            for (int e = 0; e < 4; e++) sacc[t][e] = 0.0f;

        #pragma unroll
        for (int j = 0; j < 4; j++) {
            #pragma unroll
            for (int p = 0; p < 4; p++) {
                int row = 16 * p + rt + lc * 8;
                int ch  = 2 * j + lb;
                u32 kh0, kh1, kh2, kh3, kl0, kl1, kl2, kl3;
                LDSM_X4(kh0, kh1, kh2, kh3, aKH + swz(row, ch));
                LDSM_X4(kl0, kl1, kl2, kl3, aKL + swz(row, ch));
                mma_bf16(sacc[2*p],   qh[j], kh0, kh1);
                mma_bf16(sacc[2*p],   ql[j], kh0, kh1);
                mma_bf16(sacc[2*p],   qh[j], kl0, kl1);
                mma_bf16(sacc[2*p+1], qh[j], kh2, kh3);
                mma_bf16(sacc[2*p+1], ql[j], kh2, kh3);
                mma_bf16(sacc[2*p+1], qh[j], kl2, kl3);
            }
        }

        // ---- online softmax in log2 domain ----
        float mlo = -CUDART_INF_F, mhi = -CUDART_INF_F;
        #pragma unroll
        for (int t = 0; t < 8; t++) {
            mlo = fmaxf(mlo, fmaxf(sacc[t][0], sacc[t][1]));
            mhi = fmaxf(mhi, fmaxf(sacc[t][2], sacc[t][3]));
        }
        mlo = fmaxf(mlo, __shfl_xor_sync(0xffffffffu, mlo, 1));
        mlo = fmaxf(mlo, __shfl_xor_sync(0xffffffffu, mlo, 2));
        mhi = fmaxf(mhi, __shfl_xor_sync(0xffffffffu, mhi, 1));
        mhi = fmaxf(mhi, __shfl_xor_sync(0xffffffffu, mhi, 2));

        float mnlo = fmaxf(m_lo, mlo), mnhi = fmaxf(m_hi, mhi);
        float clo = ex2f(m_lo - mnlo), chi = ex2f(m_hi - mnhi);
        m_lo = mnlo; m_hi = mnhi;

        u32 ph[8][2], pl[8][2];
        float alo = 0.0f, ahi = 0.0f;
        #pragma unroll
        for (int t = 0; t < 8; t++) {
            float p0 = ex2f(sacc[t][0] - mnlo);
            float p1 = ex2f(sacc[t][1] - mnlo);
            float p2 = ex2f(sacc[t][2] - mnhi);
            float p3 = ex2f(sacc[t][3] - mnhi);
            alo += p0 + p1; ahi += p2 + p3;
            u32 h0 = cvt2(p1, p0), h1 = cvt2(p3, p2);
            ph[t][0] = h0; ph[t][1] = h1;
            pl[t][0] = cvt2(p1 - bfhi(h0), p0 - bflo(h0));
            pl[t][1] = cvt2(p3 - bfhi(h1), p2 - bflo(h1));
        }
        l_lo = l_lo * clo + alo;
        l_hi = l_hi * chi + ahi;

        #pragma unroll
        for (int t = 0; t < 8; t++) {
            oacc[t][0] *= clo; oacc[t][1] *= clo;
            oacc[t][2] *= chi; oacc[t][3] *= chi;
        }

        #pragma unroll
        for (int j = 0; j < 4; j++) {
            u32 pa[4] = {ph[2*j][0], ph[2*j][1], ph[2*j+1][0], ph[2*j+1][1]};
            u32 pb[4] = {pl[2*j][0], pl[2*j][1], pl[2*j+1][0], pl[2*j+1][1]};
            int row = 16 * j + rt + lb * 8;
            #pragma unroll
            for (int t = 0; t < 4; t++) {
                int ch = 2 * t + lc;
                u32 vh0, vh1, vh2, vh3, vl0, vl1, vl2, vl3;
                LDSM_X4T(vh0, vh1, vh2, vh3, aVH + swz(row, ch));
                LDSM_X4T(vl0, vl1, vl2, vl3, aVL + swz(row, ch));
                mma_bf16(oacc[2*t],   pa, vh0, vh1);
                mma_bf16(oacc[2*t],   pb, vh0, vh1);
                mma_bf16(oacc[2*t],   pa, vl0, vl1);
                mma_bf16(oacc[2*t+1], pa, vh2, vh3);
                mma_bf16(oacc[2*t+1], pb, vh2, vh3);
                mma_bf16(oacc[2*t+1], pa, vl2, vl3);
            }
        }

        __syncthreads();
        if (it + 2 < NT) {
            u32 bb2 = sb + BUF_OFF + (it & 1) * BUF_STRIDE;
            int j2 = (it + 2) * 64;
            #pragma unroll
            for (int m = 0; m < 4; m++)
                #pragma unroll
                for (int i = 0; i < 4; i++) {
                    int idx = tid + i * 128;
                    int r = idx >> 3, c = idx & 7;
                    cp16(bb2 + m * 8192 + swz(r, c),
                         kvsrc[m] + (size_t)(j2 + r) * 32 + c * 4);
                }
        }
        CP_COMMIT();
    }

    // ---- epilogue: normalize, split to bf16 hi/lo, write g_Ah/g_Al ----
    float llo = l_lo + __shfl_xor_sync(0xffffffffu, l_lo, 1);
    llo += __shfl_xor_sync(0xffffffffu, llo, 2);
    float lhi = l_hi + __shfl_xor_sync(0xffffffffu, l_hi, 1);
    lhi += __shfl_xor_sync(0xffffffffu, lhi, 2);
    const float ilo = 1.0f / llo, ihi = 1.0f / lhi;

    const int bb = bh >> 2, h = bh & 3;
    const int rlo = q0 + w * 16 + (L >> 4 == 0 ? 0 : 0) + (L >> 2);
    const size_t rw0 = ((size_t)(bb * S_) + rlo) * ROW_WORDS + h * 32 + (L & 3);
    const size_t rw1 = rw0 + 8 * ROW_WORDS;
    #pragma unroll
    for (int t = 0; t < 8; t++) {
        float o0 = oacc[t][0] * ilo, o1 = oacc[t][1] * ilo;
        float o2 = oacc[t][2] * ihi, o3 = oacc[t][3] * ihi;
        u32 h0 = cvt2(o1, o0), h1 = cvt2(o3, o2);
        g_Ah[rw0 + 4 * t] = h0;
        g_Al[rw0 + 4 * t] = cvt2(o1 - bfhi(h0), o0 - bflo(h0));
        g_Ah[rw1 + 4 * t] = h1;
        g_Al[rw1 + 4 * t] = cvt2(o3 - bfhi(h1), o2 - bflo(h1));
    }
}

// ---------------------------------------------------------------------------
// Launch
// ---------------------------------------------------------------------------
extern "C" void kernel_launch(void* const* d_in, const int* in_sizes, int n_in,
                              void* d_out, int out_size)
{
    const float* X  = (const float*)d_in[0];
    const float* Wq = (const float*)d_in[1];
    const float* bq = (const float*)d_in[2];
    const float* Wk = (const float*)d_in[3];
    const float* bk = (const float*)d_in[4];
    const float* Wv = (const float*)d_in[5];
    const float* bv = (const float*)d_in[6];
    const float* Wo = (const float*)d_in[7];
    const float* bo = (const float*)d_in[8];
    float* out = (float*)d_out;

    cudaFuncSetAttribute(attn_kernel,
                         cudaFuncAttributeMaxDynamicSharedMemorySize, ATTN_SMEM);
    cudaFuncSetAttribute(qkv_hmma,
                         cudaFuncAttributeMaxDynamicSharedMemorySize, GEMM_SMEM);
    cudaFuncSetAttribute(out_hmma,
                         cudaFuncAttributeMaxDynamicSharedMemorySize, GEMM_SMEM);

    prep_kernel<<<(XWORDS + WWORDS + 255) / 256, 256>>>(X, Wq, Wk, Wv, Wo);
    qkv_hmma<<<dim3(MT_ / 128, H_, 3), 128, GEMM_SMEM>>>(bq, bk, bv);
    attn_kernel<<<dim3(S_ / 64, BH_), 128, ATTN_SMEM>>>();
    out_hmma<<<dim3(MT_ / 128, 4), 128, GEMM_SMEM>>>(bo, out);
}

// round 6
// speedup vs baseline: 5.7019x; 1.1231x over previous
#include <cuda_runtime.h>
#include <cuda_bf16.h>
#include <math_constants.h>

#define B_  4
#define S_  4096
#define D_  256
#define H_  4
#define DH_ 64
#define MT_ (B_ * S_)
#define BH_ (B_ * H_)
#define LOG2E 1.4426950408889634f

typedef unsigned int       u32;
typedef unsigned long long u64;

// ---------------------------------------------------------------------------
// Scratch: everything bf16 hi/lo split, packed u32 = {hi16: odd col, lo16: even}
// ---------------------------------------------------------------------------
#define QKV_WORDS ((size_t)BH_ * S_ * (DH_ / 2))
#define ROW_WORDS (D_ / 2)
__device__ u32 g_Qh[QKV_WORDS];  __device__ u32 g_Ql[QKV_WORDS];
__device__ u32 g_Kh[QKV_WORDS];  __device__ u32 g_Kl[QKV_WORDS];
__device__ u32 g_Vh[QKV_WORDS];  __device__ u32 g_Vl[QKV_WORDS];
__device__ u32 g_Xh[(size_t)MT_ * ROW_WORDS];
__device__ u32 g_Xl[(size_t)MT_ * ROW_WORDS];
__device__ u32 g_Ah[(size_t)MT_ * ROW_WORDS];
__device__ u32 g_Al[(size_t)MT_ * ROW_WORDS];
__device__ u32 g_Wth[4 * 256 * ROW_WORDS];
__device__ u32 g_Wtl[4 * 256 * ROW_WORDS];

// ---------------------------------------------------------------------------
// PTX helpers (baseline PTX only)
// ---------------------------------------------------------------------------
__device__ __forceinline__ u32 smem_u32(const void* p) {
    u32 a;
    asm("{ .reg .u64 t; cvta.to.shared.u64 t, %1; cvt.u32.u64 %0, t; }"
        : "=r"(a) : "l"(p));
    return a;
}
__device__ __forceinline__ u32 cvt2(float a, float b) {   // {hi=bf16(a), lo=bf16(b)}
    u32 r;
    asm("cvt.rn.bf16x2.f32 %0, %1, %2;" : "=r"(r) : "f"(a), "f"(b));
    return r;
}
__device__ __forceinline__ float bflo(u32 w) { return __uint_as_float(w << 16); }
__device__ __forceinline__ float bfhi(u32 w) { return __uint_as_float(w & 0xffff0000u); }
__device__ __forceinline__ float ex2f(float x) {
    float y; asm("ex2.approx.f32 %0, %1;" : "=f"(y) : "f"(x)); return y;
}
__device__ __forceinline__ void mma_bf16(float c[4], const u32 a[4], u32 b0, u32 b1) {
    asm volatile(
        "mma.sync.aligned.m16n8k16.row.col.f32.bf16.bf16.f32 "
        "{%0,%1,%2,%3},{%4,%5,%6,%7},{%8,%9},{%0,%1,%2,%3};"
        : "+f"(c[0]), "+f"(c[1]), "+f"(c[2]), "+f"(c[3])
        : "r"(a[0]), "r"(a[1]), "r"(a[2]), "r"(a[3]), "r"(b0), "r"(b1));
}
#define LDSM_X4(r0, r1, r2, r3, a) \
    asm volatile("ldmatrix.sync.aligned.m8n8.x4.shared.b16 {%0,%1,%2,%3}, [%4];" \
                 : "=r"(r0), "=r"(r1), "=r"(r2), "=r"(r3) : "r"(a))
#define LDSM_A(fr, a) LDSM_X4(fr[0], fr[1], fr[2], fr[3], a)
#define LDSM_X4T(r0, r1, r2, r3, a) \
    asm volatile("ldmatrix.sync.aligned.m8n8.x4.trans.shared.b16 {%0,%1,%2,%3}, [%4];" \
                 : "=r"(r0), "=r"(r1), "=r"(r2), "=r"(r3) : "r"(a))
__device__ __forceinline__ void cp16(u32 dst, const void* src) {
    asm volatile("cp.async.cg.shared.global [%0], [%1], 16;" :: "r"(dst), "l"(src));
}
#define CP_COMMIT() asm volatile("cp.async.commit_group;" ::: "memory")
#define CP_WAIT(n)  asm volatile("cp.async.wait_group %0;" :: "n"(n) : "memory")

__device__ __forceinline__ u32 swz(int row, int chunk) {
    return (u32)(row * 128 + (((chunk ^ row) & 7) << 4));
}

// ---------------------------------------------------------------------------
// Kernel 0: prep — split X; transpose+split W matrices.
// ---------------------------------------------------------------------------
#define XWORDS (2097152)
#define WWORDS (131072)
__global__ void __launch_bounds__(256) prep_kernel(
    const float* __restrict__ X,
    const float* __restrict__ Wq, const float* __restrict__ Wk,
    const float* __restrict__ Wv, const float* __restrict__ Wo)
{
    const int w = blockIdx.x * 256 + threadIdx.x;
    if (w < XWORDS) {
        float2 f = ((const float2*)X)[w];
        u32 hi = cvt2(f.y, f.x);
        g_Xh[w] = hi;
        g_Xl[w] = cvt2(f.y - bfhi(hi), f.x - bflo(hi));
    } else if (w < XWORDS + WWORDS) {
        int u = w - XWORDS;
        int z = u >> 15, r = u & 32767;
        int n = r >> 7, kp = r & 127;
        const float* Wm = (z == 0) ? Wq : (z == 1) ? Wk : (z == 2) ? Wv : Wo;
        float f0 = Wm[(size_t)(2 * kp)     * 256 + n];
        float f1 = Wm[(size_t)(2 * kp + 1) * 256 + n];
        u32 hi = cvt2(f1, f0);
        g_Wth[u] = hi;
        g_Wtl[u] = cvt2(f1 - bfhi(hi), f0 - bflo(hi));
    }
}

// ---------------------------------------------------------------------------
// HMMA GEMM core (unchanged from R5).
// ---------------------------------------------------------------------------
#define GB_AH 0
#define GB_AL 16384
#define GB_BH 32768
#define GB_BL 40960
#define GBUF  49152
#define GEMM_SMEM (2 * GBUF)

__device__ __forceinline__ void gemm_stage(u32 sb, int bufi, int kb,
                                           const u32* Ah, const u32* Al,
                                           const u32* Bh, const u32* Bl,
                                           int m0, int n0, int tid)
{
    const u32 bufb = sb + bufi * GBUF;
    #pragma unroll
    for (int i = 0; i < 8; i++) {
        int idx = tid + i * 128;
        int r = idx >> 3, c = idx & 7;
        const size_t go = (size_t)(m0 + r) * ROW_WORDS + kb * 32 + c * 4;
        cp16(bufb + GB_AH + swz(r, c), Ah + go);
        cp16(bufb + GB_AL + swz(r, c), Al + go);
    }
    #pragma unroll
    for (int i = 0; i < 4; i++) {
        int idx = tid + i * 128;
        int r = idx >> 3, c = idx & 7;
        const size_t go = (size_t)(n0 + r) * ROW_WORDS + kb * 32 + c * 4;
        cp16(bufb + GB_BH + swz(r, c), Bh + go);
        cp16(bufb + GB_BL + swz(r, c), Bl + go);
    }
}

__device__ __forceinline__ void gemm_main(u32 sb, float acc[2][8][4],
                                          const u32* Ah, const u32* Al,
                                          const u32* Bh, const u32* Bl,
                                          int m0, int n0, int tid)
{
    const int w  = tid >> 5;
    const int L  = tid & 31;
    const int rt = L & 7;
    const int lb = (L >> 3) & 1;
    const int lc = L >> 4;

    gemm_stage(sb, 0, 0, Ah, Al, Bh, Bl, m0, n0, tid);
    CP_COMMIT();
    gemm_stage(sb, 1, 1, Ah, Al, Bh, Bl, m0, n0, tid);
    CP_COMMIT();

    for (int kb = 0; kb < 4; kb++) {
        CP_WAIT(1);
        __syncthreads();
        const u32 bufb = sb + (kb & 1) * GBUF;
        const u32 aAH = bufb + GB_AH, aAL = bufb + GB_AL;
        const u32 aBH = bufb + GB_BH, aBL = bufb + GB_BL;

        #pragma unroll
        for (int j = 0; j < 4; j++) {
            u32 ah[2][4], al[2][4];
            #pragma unroll
            for (int mt = 0; mt < 2; mt++) {
                int row = w * 32 + mt * 16 + rt + lb * 8;
                LDSM_A(ah[mt], aAH + swz(row, 2 * j + lc));
                LDSM_A(al[mt], aAL + swz(row, 2 * j + lc));
            }
            #pragma unroll
            for (int p = 0; p < 4; p++) {
                int row = 16 * p + rt + lc * 8;
                int ch  = 2 * j + lb;
                u32 bh0, bh1, bh2, bh3, bl0, bl1, bl2, bl3;
                LDSM_X4(bh0, bh1, bh2, bh3, aBH + swz(row, ch));
                LDSM_X4(bl0, bl1, bl2, bl3, aBL + swz(row, ch));
                #pragma unroll
                for (int mt = 0; mt < 2; mt++) {
                    mma_bf16(acc[mt][2*p],   ah[mt], bh0, bh1);
                    mma_bf16(acc[mt][2*p],   al[mt], bh0, bh1);
                    mma_bf16(acc[mt][2*p],   ah[mt], bl0, bl1);
                    mma_bf16(acc[mt][2*p+1], ah[mt], bh2, bh3);
                    mma_bf16(acc[mt][2*p+1], al[mt], bh2, bh3);
                    mma_bf16(acc[mt][2*p+1], ah[mt], bl2, bl3);
                }
            }
        }
        __syncthreads();
        if (kb + 2 < 4)
            gemm_stage(sb, kb & 1, kb + 2, Ah, Al, Bh, Bl, m0, n0, tid);
        CP_COMMIT();
    }
}

// ---------------------------------------------------------------------------
// Kernel 1: QKV projection via HMMA. grid (MT/128, H, 3), block 128.
// ---------------------------------------------------------------------------
__global__ void __launch_bounds__(128, 2) qkv_hmma(
    const float* __restrict__ bq, const float* __restrict__ bk,
    const float* __restrict__ bv)
{
    extern __shared__ char sm[];
    const u32 sb  = smem_u32(sm);
    const int tid = threadIdx.x;
    const int z   = blockIdx.z;
    const int h   = blockIdx.y;
    const int m0  = blockIdx.x * 128;
    const int n0  = h * 64;

    const float* bias = (z == 0) ? bq : (z == 1) ? bk : bv;
    u32* oh = (z == 0) ? g_Qh : (z == 1) ? g_Kh : g_Vh;
    u32* ol = (z == 0) ? g_Ql : (z == 1) ? g_Kl : g_Vl;
    const float qs = (z == 0) ? (0.125f * LOG2E) : 1.0f;

    float acc[2][8][4];
    #pragma unroll
    for (int mt = 0; mt < 2; mt++)
        #pragma unroll
        for (int t = 0; t < 8; t++)
            #pragma unroll
            for (int e = 0; e < 4; e++) acc[mt][t][e] = 0.0f;

    gemm_main(sb, acc, g_Xh, g_Xl,
              g_Wth + (size_t)z * 256 * ROW_WORDS,
              g_Wtl + (size_t)z * 256 * ROW_WORDS, m0, n0, tid);

    const int w  = tid >> 5;
    const int L  = tid & 31;
    const int lr = L >> 2, lcq = L & 3;
    float b2[8][2];
    #pragma unroll
    for (int t = 0; t < 8; t++) {
        b2[t][0] = bias[n0 + 8 * t + lcq * 2];
        b2[t][1] = bias[n0 + 8 * t + lcq * 2 + 1];
    }
    const int bb = m0 >> 12;
    const int sbase = m0 & (S_ - 1);
    #pragma unroll
    for (int mt = 0; mt < 2; mt++) {
        #pragma unroll
        for (int half = 0; half < 2; half++) {
            int s = sbase + w * 32 + mt * 16 + lr + half * 8;
            size_t rw = ((size_t)(bb * H_ + h) * S_ + s) * 32 + lcq;
            #pragma unroll
            for (int t = 0; t < 8; t++) {
                float v0 = (acc[mt][t][half * 2 + 0] + b2[t][0]) * qs;
                float v1 = (acc[mt][t][half * 2 + 1] + b2[t][1]) * qs;
                u32 hi = cvt2(v1, v0);
                oh[rw + 4 * t] = hi;
                ol[rw + 4 * t] = cvt2(v1 - bfhi(hi), v0 - bflo(hi));
            }
        }
    }
}

// ---------------------------------------------------------------------------
// Kernel 3: output projection via HMMA. grid (MT/128, 4), block 128.
// ---------------------------------------------------------------------------
__global__ void __launch_bounds__(128, 2) out_hmma(
    const float* __restrict__ bo, float* __restrict__ out)
{
    extern __shared__ char sm[];
    const u32 sb  = smem_u32(sm);
    const int tid = threadIdx.x;
    const int m0  = blockIdx.x * 128;
    const int n0  = blockIdx.y * 64;

    float acc[2][8][4];
    #pragma unroll
    for (int mt = 0; mt < 2; mt++)
        #pragma unroll
        for (int t = 0; t < 8; t++)
            #pragma unroll
            for (int e = 0; e < 4; e++) acc[mt][t][e] = 0.0f;

    gemm_main(sb, acc, g_Ah, g_Al,
              g_Wth + (size_t)3 * 256 * ROW_WORDS,
              g_Wtl + (size_t)3 * 256 * ROW_WORDS, m0, n0, tid);

    const int w  = tid >> 5;
    const int L  = tid & 31;
    const int lr = L >> 2, lcq = L & 3;
    float b2[8][2];
    #pragma unroll
    for (int t = 0; t < 8; t++) {
        b2[t][0] = bo[n0 + 8 * t + lcq * 2];
        b2[t][1] = bo[n0 + 8 * t + lcq * 2 + 1];
    }
    #pragma unroll
    for (int mt = 0; mt < 2; mt++) {
        #pragma unroll
        for (int half = 0; half < 2; half++) {
            int m = m0 + w * 32 + mt * 16 + lr + half * 8;
            float* orow = out + (size_t)m * D_ + n0 + lcq * 2;
            #pragma unroll
            for (int t = 0; t < 8; t++) {
                float2 v;
                v.x = acc[mt][t][half * 2 + 0] + b2[t][0];
                v.y = acc[mt][t][half * 2 + 1] + b2[t][1];
                *(float2*)&orow[8 * t] = v;
            }
        }
    }
}

// ---------------------------------------------------------------------------
// Kernel 2: flash attention. grid (S/64, BH), block 128, 3 CTAs/SM target.
// smem: just 2 KV buffers (32KB each); Q staged through buf0 in prologue.
// ---------------------------------------------------------------------------
#define BUF_STRIDE 32768
#define ATTN_SMEM  (2 * 32768)

__global__ void __launch_bounds__(128, 3) attn_kernel()
{
    extern __shared__ char sm[];
    const u32 sb  = smem_u32(sm);
    const int tid = threadIdx.x;
    const int w   = tid >> 5;
    const int L   = tid & 31;
    const int bh  = blockIdx.y;
    const int q0  = blockIdx.x * 64;

    const size_t head = (size_t)bh * S_ * (DH_ / 2);
    const u32* Qh = g_Qh + head; const u32* Ql = g_Ql + head;
    const u32* Kh = g_Kh + head; const u32* Kl = g_Kl + head;
    const u32* Vh = g_Vh + head; const u32* Vl = g_Vl + head;

    const int rt = L & 7;
    const int lb = (L >> 3) & 1;
    const int lc = L >> 4;

    // ---- prologue: stage Q through buf0, extract frags, then start KV ----
    #pragma unroll
    for (int i = 0; i < 4; i++) {
        int idx = tid + i * 128;
        int r = idx >> 3, c = idx & 7;
        cp16(sb + swz(r, c),        Qh + (size_t)(q0 + r) * 32 + c * 4);
        cp16(sb + 8192 + swz(r, c), Ql + (size_t)(q0 + r) * 32 + c * 4);
    }
    CP_COMMIT();
    CP_WAIT(0);
    __syncthreads();

    u32 qh[4][4], ql[4][4];
    #pragma unroll
    for (int j = 0; j < 4; j++) {
        int row = w * 16 + rt + lb * 8;
        LDSM_A(qh[j], sb + swz(row, 2 * j + lc));
        LDSM_A(ql[j], sb + 8192 + swz(row, 2 * j + lc));
    }
    __syncthreads();   // Q fully read before buf0 is reused for K/V

    const u32* kvsrc[4] = {Kh, Kl, Vh, Vl};
    #pragma unroll
    for (int t0 = 0; t0 < 2; t0++) {
        u32 bufb = sb + t0 * BUF_STRIDE;
        #pragma unroll
        for (int m = 0; m < 4; m++)
            #pragma unroll
            for (int i = 0; i < 4; i++) {
                int idx = tid + i * 128;
                int r = idx >> 3, c = idx & 7;
                cp16(bufb + m * 8192 + swz(r, c),
                     kvsrc[m] + (size_t)(t0 * 64 + r) * 32 + c * 4);
            }
        CP_COMMIT();
    }

    float oacc[8][4];
    #pragma unroll
    for (int t = 0; t < 8; t++)
        #pragma unroll
        for (int e = 0; e < 4; e++) oacc[t][e] = 0.0f;
    float m_lo = -CUDART_INF_F, m_hi = -CUDART_INF_F;
    float l_lo = 0.0f, l_hi = 0.0f;

    const int NT = S_ / 64;
    for (int it = 0; it < NT; it++) {
        CP_WAIT(1);
        __syncthreads();
        const u32 bufb = sb + (it & 1) * BUF_STRIDE;
        const u32 aKH = bufb, aKL = bufb + 8192;
        const u32 aVH = bufb + 16384, aVL = bufb + 24576;

        // ---- S = Q K^T (3-split) ----
        float sacc[8][4];
        #pragma unroll
        for (int t = 0; t < 8; t++)
            #pragma unroll
            for (int e = 0; e < 4; e++) sacc[t][e] = 0.0f;

        #pragma unroll
        for (int j = 0; j < 4; j++) {
            #pragma unroll
            for (int p = 0; p < 4; p++) {
                int row = 16 * p + rt + lc * 8;
                int ch  = 2 * j + lb;
                u32 kh0, kh1, kh2, kh3, kl0, kl1, kl2, kl3;
                LDSM_X4(kh0, kh1, kh2, kh3, aKH + swz(row, ch));
                LDSM_X4(kl0, kl1, kl2, kl3, aKL + swz(row, ch));
                mma_bf16(sacc[2*p],   qh[j], kh0, kh1);
                mma_bf16(sacc[2*p+1], qh[j], kh2, kh3);
                mma_bf16(sacc[2*p],   ql[j], kh0, kh1);
                mma_bf16(sacc[2*p+1], ql[j], kh2, kh3);
                mma_bf16(sacc[2*p],   qh[j], kl0, kl1);
                mma_bf16(sacc[2*p+1], qh[j], kl2, kl3);
            }
        }

        // ---- row max (log2 domain) ----
        float mlo = -CUDART_INF_F, mhi = -CUDART_INF_F;
        #pragma unroll
        for (int t = 0; t < 8; t++) {
            mlo = fmaxf(mlo, fmaxf(sacc[t][0], sacc[t][1]));
            mhi = fmaxf(mhi, fmaxf(sacc[t][2], sacc[t][3]));
        }
        mlo = fmaxf(mlo, __shfl_xor_sync(0xffffffffu, mlo, 1));
        mlo = fmaxf(mlo, __shfl_xor_sync(0xffffffffu, mlo, 2));
        mhi = fmaxf(mhi, __shfl_xor_sync(0xffffffffu, mhi, 1));
        mhi = fmaxf(mhi, __shfl_xor_sync(0xffffffffu, mhi, 2));

        float mnlo = fmaxf(m_lo, mlo), mnhi = fmaxf(m_hi, mhi);
        float clo = ex2f(m_lo - mnlo), chi = ex2f(m_hi - mnhi);
        m_lo = mnlo; m_hi = mnhi;

        #pragma unroll
        for (int t = 0; t < 8; t++) {
            oacc[t][0] *= clo; oacc[t][1] *= clo;
            oacc[t][2] *= chi; oacc[t][3] *= chi;
        }

        // ---- PV with just-in-time P conversion (saves 32 registers) ----
        float alo = 0.0f, ahi = 0.0f;
        #pragma unroll
        for (int j = 0; j < 4; j++) {
            u32 pa[4], pb[4];
            #pragma unroll
            for (int tt = 0; tt < 2; tt++) {
                const float* sv = sacc[2 * j + tt];
                float p0 = ex2f(sv[0] - mnlo);
                float p1 = ex2f(sv[1] - mnlo);
                float p2 = ex2f(sv[2] - mnhi);
                float p3 = ex2f(sv[3] - mnhi);
                alo += p0 + p1; ahi += p2 + p3;
                u32 h0 = cvt2(p1, p0), h1 = cvt2(p3, p2);
                pa[2 * tt]     = h0;
                pa[2 * tt + 1] = h1;
                pb[2 * tt]     = cvt2(p1 - bfhi(h0), p0 - bflo(h0));
                pb[2 * tt + 1] = cvt2(p3 - bfhi(h1), p2 - bflo(h1));
            }
            int row = 16 * j + rt + lb * 8;
            #pragma unroll
            for (int t = 0; t < 4; t++) {
                int ch = 2 * t + lc;
                u32 vh0, vh1, vh2, vh3, vl0, vl1, vl2, vl3;
                LDSM_X4T(vh0, vh1, vh2, vh3, aVH + swz(row, ch));
                LDSM_X4T(vl0, vl1, vl2, vl3, aVL + swz(row, ch));
                mma_bf16(oacc[2*t],   pa, vh0, vh1);
                mma_bf16(oacc[2*t+1], pa, vh2, vh3);
                mma_bf16(oacc[2*t],   pb, vh0, vh1);
                mma_bf16(oacc[2*t+1], pb, vh2, vh3);
                mma_bf16(oacc[2*t],   pa, vl0, vl1);
                mma_bf16(oacc[2*t+1], pa, vl2, vl3);
            }
        }
        l_lo = l_lo * clo + alo;
        l_hi = l_hi * chi + ahi;

        __syncthreads();
        if (it + 2 < NT) {
            u32 bb2 = sb + (it & 1) * BUF_STRIDE;
            int j2 = (it + 2) * 64;
            #pragma unroll
            for (int m = 0; m < 4; m++)
                #pragma unroll
                for (int i = 0; i < 4; i++) {
                    int idx = tid + i * 128;
                    int r = idx >> 3, c = idx & 7;
                    cp16(bb2 + m * 8192 + swz(r, c),
                         kvsrc[m] + (size_t)(j2 + r) * 32 + c * 4);
                }
        }
        CP_COMMIT();
    }

    // ---- epilogue: normalize, split to bf16 hi/lo, write g_Ah/g_Al ----
    float llo = l_lo + __shfl_xor_sync(0xffffffffu, l_lo, 1);
    llo += __shfl_xor_sync(0xffffffffu, llo, 2);
    float lhi = l_hi + __shfl_xor_sync(0xffffffffu, l_hi, 1);
    lhi += __shfl_xor_sync(0xffffffffu, lhi, 2);
    const float ilo = 1.0f / llo, ihi = 1.0f / lhi;

    const int bb = bh >> 2, h = bh & 3;
    const int rlo = q0 + w * 16 + (L >> 2);
    const size_t rw0 = ((size_t)(bb * S_) + rlo) * ROW_WORDS + h * 32 + (L & 3);
    const size_t rw1 = rw0 + 8 * ROW_WORDS;
    #pragma unroll
    for (int t = 0; t < 8; t++) {
        float o0 = oacc[t][0] * ilo, o1 = oacc[t][1] * ilo;
        float o2 = oacc[t][2] * ihi, o3 = oacc[t][3] * ihi;
        u32 h0 = cvt2(o1, o0), h1 = cvt2(o3, o2);
        g_Ah[rw0 + 4 * t] = h0;
        g_Al[rw0 + 4 * t] = cvt2(o1 - bfhi(h0), o0 - bflo(h0));
        g_Ah[rw1 + 4 * t] = h1;
        g_Al[rw1 + 4 * t] = cvt2(o3 - bfhi(h1), o2 - bflo(h1));
    }
}

// ---------------------------------------------------------------------------
// Launch
// ---------------------------------------------------------------------------
extern "C" void kernel_launch(void* const* d_in, const int* in_sizes, int n_in,
                              void* d_out, int out_size)
{
    const float* X  = (const float*)d_in[0];
    const float* Wq = (const float*)d_in[1];
    const float* bq = (const float*)d_in[2];
    const float* Wk = (const float*)d_in[3];
    const float* bk = (const float*)d_in[4];
    const float* Wv = (const float*)d_in[5];
    const float* bv = (const float*)d_in[6];
    const float* Wo = (const float*)d_in[7];
    const float* bo = (const float*)d_in[8];
    float* out = (float*)d_out;

    cudaFuncSetAttribute(attn_kernel,
                         cudaFuncAttributeMaxDynamicSharedMemorySize, ATTN_SMEM);
    cudaFuncSetAttribute(qkv_hmma,
                         cudaFuncAttributeMaxDynamicSharedMemorySize, GEMM_SMEM);
    cudaFuncSetAttribute(out_hmma,
                         cudaFuncAttributeMaxDynamicSharedMemorySize, GEMM_SMEM);

    prep_kernel<<<(XWORDS + WWORDS + 255) / 256, 256>>>(X, Wq, Wk, Wv, Wo);
    qkv_hmma<<<dim3(MT_ / 128, H_, 3), 128, GEMM_SMEM>>>(bq, bk, bv);
    attn_kernel<<<dim3(S_ / 64, BH_), 128, ATTN_SMEM>>>();
    out_hmma<<<dim3(MT_ / 128, 4), 128, GEMM_SMEM>>>(bo, out);
}